// round 7
// baseline (speedup 1.0000x reference)
#include <cuda_runtime.h>
#include <cuda_fp16.h>
#include <cstdint>

// ---------------------------------------------------------------------------
// LightOnOcrPatchMerger: 2x2 patch merge (unfold) + Linear(4096 -> 1024).
//   1) pack_A: gather feats rows into merged fp16 A'[16860][4096], column
//      order c' = q*1024 + d  -> contiguous row copies (near DRAM roofline).
//   2) pack_W: permute W columns to same order, fp32 -> fp16.
//   3) gemm:   out = A' * W'^T via mma.sync m16n8k16 (fp32 accum).
//      128x256 CTA tile, 64x64 warp tiles, BK=32, 4-stage cp.async pipeline.
// NOTE: tcgen05/TMEM is NOT available — harness PTX target is sm_103 (no 'a'),
// which rejects all arch-accelerated instructions. mma.sync is the tensor path.
// ---------------------------------------------------------------------------

#define M_TOTAL 16860
#define N_TOTAL 1024
#define K_TOTAL 4096
#define HID     1024

__constant__ int c_moff[8] = {0, 3025, 5225, 6985, 8245, 11161, 13361, 14385};
__constant__ int c_foff[8] = {0, 12100, 20900, 27940, 32980, 44644, 53444, 57540};
__constant__ int c_wp[8]   = {110, 110, 64, 90, 108, 80, 64, 110};

__device__ __align__(16) __half g_A[(size_t)M_TOTAL * K_TOTAL];  // 138 MB
__device__ __align__(16) __half g_W[(size_t)N_TOTAL * K_TOTAL];  // 8 MB

// ---------------------------------------------------------------------------
__global__ void pack_A_kernel(const float* __restrict__ feats) {
    int t = blockIdx.x;
    int img = 0;
#pragma unroll
    for (int i = 1; i < 8; ++i)
        if (t >= c_moff[i]) img = i;
    int tl = t - c_moff[img];
    int wp = c_wp[img];
    int hw = wp >> 1;
    int bi = tl / hw;
    int bj = tl - bi * hw;
    int base = c_foff[img] + (2 * bi) * wp + 2 * bj;

    int tid = threadIdx.x;
#pragma unroll
    for (int q = 0; q < 4; ++q) {
        int r = base + (q >> 1) * wp + (q & 1);
        const float4* src = reinterpret_cast<const float4*>(feats + (size_t)r * HID);
        float4 v = src[tid];
        __half2 h0 = __floats2half2_rn(v.x, v.y);
        __half2 h1 = __floats2half2_rn(v.z, v.w);
        __half2* dst = reinterpret_cast<__half2*>(g_A + (size_t)t * K_TOTAL + q * HID) + tid * 2;
        dst[0] = h0;
        dst[1] = h1;
    }
}

__global__ void pack_W_kernel(const float* __restrict__ W) {
    int idx = blockIdx.x * blockDim.x + threadIdx.x;
    int o = idx >> 12;
    int c = idx & 4095;
    int q = c >> 10;
    int d = c & 1023;
    g_W[idx] = __float2half(W[(size_t)o * 4096 + d * 4 + q]);
}

// ---------------------------------------------------------------------------
// GEMM: 128x256 CTA, 8 warps (2 M x 4 N), warp tile 64x64, BK=32, 4 stages.
// ---------------------------------------------------------------------------
#define BM 128
#define BN 256
#define BK 32
#define NSTAGE 4
#define SPAD 8
#define SSTRIDE (BK + SPAD)            // 40 halves = 80B row stride
#define KT (K_TOTAL / BK)              // 128 iterations

#define A_STAGE_H (BM * SSTRIDE)       // 5120 halves
#define B_STAGE_H (BN * SSTRIDE)       // 10240 halves
#define STAGE_H   (A_STAGE_H + B_STAGE_H)
#define SMEM_BYTES (NSTAGE * STAGE_H * 2)   // 122880 B

__device__ __forceinline__ void cp_async16(void* smem, const void* gmem, bool pred) {
    uint32_t s = (uint32_t)__cvta_generic_to_shared(smem);
    int sz = pred ? 16 : 0;
    asm volatile("cp.async.cg.shared.global [%0], [%1], 16, %2;\n"
                 :: "r"(s), "l"(gmem), "r"(sz));
}

__device__ __forceinline__ void ldmatrix_x4(uint32_t& r0, uint32_t& r1,
                                            uint32_t& r2, uint32_t& r3,
                                            const void* ptr) {
    uint32_t addr = (uint32_t)__cvta_generic_to_shared(ptr);
    asm volatile("ldmatrix.sync.aligned.m8n8.x4.shared.b16 {%0,%1,%2,%3}, [%4];"
                 : "=r"(r0), "=r"(r1), "=r"(r2), "=r"(r3)
                 : "r"(addr));
}

__device__ __forceinline__ void mma_16816(float* c, const uint32_t* a,
                                          uint32_t b0, uint32_t b1) {
    asm volatile(
        "mma.sync.aligned.m16n8k16.row.col.f32.f16.f16.f32 "
        "{%0,%1,%2,%3}, {%4,%5,%6,%7}, {%8,%9}, {%0,%1,%2,%3};\n"
        : "+f"(c[0]), "+f"(c[1]), "+f"(c[2]), "+f"(c[3])
        : "r"(a[0]), "r"(a[1]), "r"(a[2]), "r"(a[3]), "r"(b0), "r"(b1));
}

__global__ __launch_bounds__(256, 1) void gemm_kernel(float* __restrict__ out) {
    extern __shared__ __align__(16) __half smem[];

    const int tid  = threadIdx.x;
    const int warp = tid >> 5;
    const int lane = tid & 31;
    const int wm = warp >> 2;  // 0..1 -> 64-row slice
    const int wn = warp & 3;   // 0..3 -> 64-col slice

    const int mbase = blockIdx.y * BM;
    const int nbase = blockIdx.x * BN;

    float acc[4][8][4];
#pragma unroll
    for (int i = 0; i < 4; ++i)
#pragma unroll
        for (int j = 0; j < 8; ++j)
#pragma unroll
            for (int k = 0; k < 4; ++k) acc[i][j][k] = 0.f;

    // ---- stage loader: A 128x32 (512 x 16B) + B 256x32 (1024 x 16B), 256 thr
    auto load_stage = [&](int s, int kt) {
        const int kbase = kt * BK;
        __half* sA = smem + s * STAGE_H;
        __half* sB = sA + A_STAGE_H;
        // A: 2 chunks per thread
#pragma unroll
        for (int it = 0; it < 2; ++it) {
            int cid = tid + it * 256;
            int row = cid >> 2;         // 0..127
            int c16 = cid & 3;          // 4 x 16B per row
            int gr = mbase + row;
            const __half* src = g_A + (size_t)gr * K_TOTAL + kbase + c16 * 8;
            cp_async16(&sA[row * SSTRIDE + c16 * 8], src, gr < M_TOTAL);
        }
        // B: 4 chunks per thread
#pragma unroll
        for (int it = 0; it < 4; ++it) {
            int cid = tid + it * 256;
            int row = cid >> 2;         // 0..255
            int c16 = cid & 3;
            const __half* src = g_W + (size_t)(nbase + row) * K_TOTAL + kbase + c16 * 8;
            cp_async16(&sB[row * SSTRIDE + c16 * 8], src, true);
        }
    };

    // ---- prologue: stages 0..2
#pragma unroll
    for (int s = 0; s < NSTAGE - 1; ++s) {
        load_stage(s, s);
        asm volatile("cp.async.commit_group;\n");
    }

    const int lr = lane & 15;
    const int lc = (lane >> 4) << 3;

    for (int kt = 0; kt < KT; ++kt) {
        asm volatile("cp.async.wait_group %0;\n" :: "n"(NSTAGE - 2));
        __syncthreads();

        // issue next loads (stage kt+3) before compute; commit every iter
        if (kt + NSTAGE - 1 < KT)
            load_stage((kt + NSTAGE - 1) % NSTAGE, kt + NSTAGE - 1);
        asm volatile("cp.async.commit_group;\n");

        const int s = kt % NSTAGE;
        const __half* sA = smem + s * STAGE_H;
        const __half* sB = sA + A_STAGE_H;

#pragma unroll
        for (int ks = 0; ks < 2; ++ks) {
            uint32_t a[4][4];
            uint32_t b[4][4];
#pragma unroll
            for (int mt = 0; mt < 4; ++mt)
                ldmatrix_x4(a[mt][0], a[mt][1], a[mt][2], a[mt][3],
                            &sA[(wm * 64 + mt * 16 + lr) * SSTRIDE + ks * 16 + lc]);
#pragma unroll
            for (int nt2 = 0; nt2 < 4; ++nt2)
                ldmatrix_x4(b[nt2][0], b[nt2][1], b[nt2][2], b[nt2][3],
                            &sB[(wn * 64 + nt2 * 16 + lr) * SSTRIDE + ks * 16 + lc]);
#pragma unroll
            for (int mt = 0; mt < 4; ++mt)
#pragma unroll
                for (int nt2 = 0; nt2 < 4; ++nt2) {
                    mma_16816(acc[mt][nt2 * 2 + 0], a[mt], b[nt2][0], b[nt2][2]);
                    mma_16816(acc[mt][nt2 * 2 + 1], a[mt], b[nt2][1], b[nt2][3]);
                }
        }
    }

    // ---- epilogue: direct fp32 stores (float2 per fragment half)
#pragma unroll
    for (int mt = 0; mt < 4; ++mt) {
#pragma unroll
        for (int nt = 0; nt < 8; ++nt) {
            int r0 = mbase + wm * 64 + mt * 16 + (lane >> 2);
            int col = nbase + wn * 64 + nt * 8 + ((lane & 3) << 1);
            if (r0 < M_TOTAL) {
                float2 v = {acc[mt][nt][0], acc[mt][nt][1]};
                *reinterpret_cast<float2*>(&out[(size_t)r0 * N_TOTAL + col]) = v;
            }
            int r1 = r0 + 8;
            if (r1 < M_TOTAL) {
                float2 v = {acc[mt][nt][2], acc[mt][nt][3]};
                *reinterpret_cast<float2*>(&out[(size_t)r1 * N_TOTAL + col]) = v;
            }
        }
    }
}

// ---------------------------------------------------------------------------
extern "C" void kernel_launch(void* const* d_in, const int* in_sizes, int n_in,
                              void* d_out, int out_size) {
    const float* feats = (const float*)d_in[0];   // [67440, 1024] fp32
    const float* W     = (const float*)d_in[1];   // [1024, 4096]  fp32
    float* out = (float*)d_out;                   // [16860, 1024] fp32

    pack_A_kernel<<<M_TOTAL, 256>>>(feats);
    pack_W_kernel<<<(N_TOTAL * K_TOTAL) / 256, 256>>>(W);

    cudaFuncSetAttribute(gemm_kernel,
                         cudaFuncAttributeMaxDynamicSharedMemorySize, SMEM_BYTES);
    dim3 grid(N_TOTAL / BN, (M_TOTAL + BM - 1) / BM);  // N fastest -> A L2 reuse
    gemm_kernel<<<grid, 256, SMEM_BYTES>>>(out);
}

// round 9
// speedup vs baseline: 1.1136x; 1.1136x over previous
#include <cuda_runtime.h>
#include <cuda_fp16.h>
#include <cstdint>

// ---------------------------------------------------------------------------
// LightOnOcrPatchMerger: 2x2 patch merge (unfold) + Linear(4096 -> 1024).
//   1) pack_A: gather feats rows into merged fp16 A'[16860][4096], column
//      order c' = q*1024 + d  -> contiguous row copies (near DRAM roofline).
//   2) pack_W: permute W columns to same order, fp32 -> fp16.
//   3) gemm:   out = A' * W'^T via mma.sync m16n8k16 (fp32 accum).
//      128x128 CTA tile, 4 warps of 64x64, BK=32, 4-stage cp.async pipeline,
//      2 CTAs/SM. (tcgen05 unavailable: harness PTX target is sm_103, no 'a'.)
// R8 note: identical to R7 submission — that bench died to a container
// failure, not a kernel issue; resubmitting to get the measurement.
// ---------------------------------------------------------------------------

#define M_TOTAL 16860
#define N_TOTAL 1024
#define K_TOTAL 4096
#define HID     1024

__constant__ int c_moff[8] = {0, 3025, 5225, 6985, 8245, 11161, 13361, 14385};
__constant__ int c_foff[8] = {0, 12100, 20900, 27940, 32980, 44644, 53444, 57540};
__constant__ int c_wp[8]   = {110, 110, 64, 90, 108, 80, 64, 110};

__device__ __align__(16) __half g_A[(size_t)M_TOTAL * K_TOTAL];  // 138 MB
__device__ __align__(16) __half g_W[(size_t)N_TOTAL * K_TOTAL];  // 8 MB

// ---------------------------------------------------------------------------
__global__ void pack_A_kernel(const float* __restrict__ feats) {
    int t = blockIdx.x;
    int img = 0;
#pragma unroll
    for (int i = 1; i < 8; ++i)
        if (t >= c_moff[i]) img = i;
    int tl = t - c_moff[img];
    int wp = c_wp[img];
    int hw = wp >> 1;
    int bi = tl / hw;
    int bj = tl - bi * hw;
    int base = c_foff[img] + (2 * bi) * wp + 2 * bj;

    int tid = threadIdx.x;
#pragma unroll
    for (int q = 0; q < 4; ++q) {
        int r = base + (q >> 1) * wp + (q & 1);
        const float4* src = reinterpret_cast<const float4*>(feats + (size_t)r * HID);
        float4 v = src[tid];
        __half2 h0 = __floats2half2_rn(v.x, v.y);
        __half2 h1 = __floats2half2_rn(v.z, v.w);
        __half2* dst = reinterpret_cast<__half2*>(g_A + (size_t)t * K_TOTAL + q * HID) + tid * 2;
        dst[0] = h0;
        dst[1] = h1;
    }
}

__global__ void pack_W_kernel(const float* __restrict__ W) {
    int idx = blockIdx.x * blockDim.x + threadIdx.x;
    int o = idx >> 12;
    int c = idx & 4095;
    int q = c >> 10;
    int d = c & 1023;
    g_W[idx] = __float2half(W[(size_t)o * 4096 + d * 4 + q]);
}

// ---------------------------------------------------------------------------
// GEMM: 128x128 CTA, 4 warps (2 M x 2 N), warp tile 64x64, BK=32, 4 stages.
// ---------------------------------------------------------------------------
#define BM 128
#define BN 128
#define BK 32
#define NSTAGE 4
#define SPAD 8
#define SSTRIDE (BK + SPAD)            // 40 halves = 80B row stride
#define KT (K_TOTAL / BK)              // 128 iterations

#define A_STAGE_H (BM * SSTRIDE)       // 5120 halves
#define B_STAGE_H (BN * SSTRIDE)       // 5120 halves
#define STAGE_H   (A_STAGE_H + B_STAGE_H)
#define SMEM_BYTES (NSTAGE * STAGE_H * 2)   // 81920 B

__device__ __forceinline__ void cp_async16(void* smem, const void* gmem, bool pred) {
    uint32_t s = (uint32_t)__cvta_generic_to_shared(smem);
    int sz = pred ? 16 : 0;
    asm volatile("cp.async.cg.shared.global [%0], [%1], 16, %2;\n"
                 :: "r"(s), "l"(gmem), "r"(sz));
}

__device__ __forceinline__ void ldmatrix_x4(uint32_t& r0, uint32_t& r1,
                                            uint32_t& r2, uint32_t& r3,
                                            const void* ptr) {
    uint32_t addr = (uint32_t)__cvta_generic_to_shared(ptr);
    asm volatile("ldmatrix.sync.aligned.m8n8.x4.shared.b16 {%0,%1,%2,%3}, [%4];"
                 : "=r"(r0), "=r"(r1), "=r"(r2), "=r"(r3)
                 : "r"(addr));
}

__device__ __forceinline__ void mma_16816(float* c, const uint32_t* a,
                                          uint32_t b0, uint32_t b1) {
    asm volatile(
        "mma.sync.aligned.m16n8k16.row.col.f32.f16.f16.f32 "
        "{%0,%1,%2,%3}, {%4,%5,%6,%7}, {%8,%9}, {%0,%1,%2,%3};\n"
        : "+f"(c[0]), "+f"(c[1]), "+f"(c[2]), "+f"(c[3])
        : "r"(a[0]), "r"(a[1]), "r"(a[2]), "r"(a[3]), "r"(b0), "r"(b1));
}

__global__ __launch_bounds__(128, 2) void gemm_kernel(float* __restrict__ out) {
    extern __shared__ __align__(16) __half smem[];

    const int tid  = threadIdx.x;
    const int warp = tid >> 5;
    const int lane = tid & 31;
    const int wm = warp >> 1;  // 0..1 -> 64-row slice
    const int wn = warp & 1;   // 0..1 -> 64-col slice

    const int mbase = blockIdx.y * BM;
    const int nbase = blockIdx.x * BN;

    float acc[4][8][4];
#pragma unroll
    for (int i = 0; i < 4; ++i)
#pragma unroll
        for (int j = 0; j < 8; ++j)
#pragma unroll
            for (int k = 0; k < 4; ++k) acc[i][j][k] = 0.f;

    // ---- stage loader: A 128x32 + B 128x32 = 1024 x 16B chunks, 128 threads
    auto load_stage = [&](int s, int kt) {
        const int kbase = kt * BK;
        __half* sA = smem + s * STAGE_H;
        __half* sB = sA + A_STAGE_H;
#pragma unroll
        for (int it = 0; it < 4; ++it) {
            int cid = tid + it * 128;
            int row = cid >> 2;         // 0..127
            int c16 = cid & 3;
            int gr = mbase + row;
            const __half* src = g_A + (size_t)gr * K_TOTAL + kbase + c16 * 8;
            cp_async16(&sA[row * SSTRIDE + c16 * 8], src, gr < M_TOTAL);
        }
#pragma unroll
        for (int it = 0; it < 4; ++it) {
            int cid = tid + it * 128;
            int row = cid >> 2;
            int c16 = cid & 3;
            const __half* src = g_W + (size_t)(nbase + row) * K_TOTAL + kbase + c16 * 8;
            cp_async16(&sB[row * SSTRIDE + c16 * 8], src, true);
        }
    };

    // ---- prologue: stages 0..2
#pragma unroll
    for (int s = 0; s < NSTAGE - 1; ++s) {
        load_stage(s, s);
        asm volatile("cp.async.commit_group;\n");
    }

    const int lr = lane & 15;
    const int lc = (lane >> 4) << 3;

    for (int kt = 0; kt < KT; ++kt) {
        asm volatile("cp.async.wait_group %0;\n" :: "n"(NSTAGE - 2));
        __syncthreads();

        if (kt + NSTAGE - 1 < KT)
            load_stage((kt + NSTAGE - 1) % NSTAGE, kt + NSTAGE - 1);
        asm volatile("cp.async.commit_group;\n");

        const int s = kt % NSTAGE;
        const __half* sA = smem + s * STAGE_H;
        const __half* sB = sA + A_STAGE_H;

#pragma unroll
        for (int ks = 0; ks < 2; ++ks) {
            uint32_t a[4][4];
            uint32_t b[4][4];
#pragma unroll
            for (int mt = 0; mt < 4; ++mt)
                ldmatrix_x4(a[mt][0], a[mt][1], a[mt][2], a[mt][3],
                            &sA[(wm * 64 + mt * 16 + lr) * SSTRIDE + ks * 16 + lc]);
#pragma unroll
            for (int nt2 = 0; nt2 < 4; ++nt2)
                ldmatrix_x4(b[nt2][0], b[nt2][1], b[nt2][2], b[nt2][3],
                            &sB[(wn * 64 + nt2 * 16 + lr) * SSTRIDE + ks * 16 + lc]);
#pragma unroll
            for (int mt = 0; mt < 4; ++mt)
#pragma unroll
                for (int nt2 = 0; nt2 < 4; ++nt2) {
                    mma_16816(acc[mt][nt2 * 2 + 0], a[mt], b[nt2][0], b[nt2][2]);
                    mma_16816(acc[mt][nt2 * 2 + 1], a[mt], b[nt2][1], b[nt2][3]);
                }
        }
    }

    // ---- epilogue: direct fp32 stores (float2 per fragment half)
#pragma unroll
    for (int mt = 0; mt < 4; ++mt) {
#pragma unroll
        for (int nt = 0; nt < 8; ++nt) {
            int r0 = mbase + wm * 64 + mt * 16 + (lane >> 2);
            int col = nbase + wn * 64 + nt * 8 + ((lane & 3) << 1);
            if (r0 < M_TOTAL) {
                float2 v = {acc[mt][nt][0], acc[mt][nt][1]};
                *reinterpret_cast<float2*>(&out[(size_t)r0 * N_TOTAL + col]) = v;
            }
            int r1 = r0 + 8;
            if (r1 < M_TOTAL) {
                float2 v = {acc[mt][nt][2], acc[mt][nt][3]};
                *reinterpret_cast<float2*>(&out[(size_t)r1 * N_TOTAL + col]) = v;
            }
        }
    }
}

// ---------------------------------------------------------------------------
extern "C" void kernel_launch(void* const* d_in, const int* in_sizes, int n_in,
                              void* d_out, int out_size) {
    const float* feats = (const float*)d_in[0];   // [67440, 1024] fp32
    const float* W     = (const float*)d_in[1];   // [1024, 4096]  fp32
    float* out = (float*)d_out;                   // [16860, 1024] fp32

    pack_A_kernel<<<M_TOTAL, 256>>>(feats);
    pack_W_kernel<<<(N_TOTAL * K_TOTAL) / 256, 256>>>(W);

    cudaFuncSetAttribute(gemm_kernel,
                         cudaFuncAttributeMaxDynamicSharedMemorySize, SMEM_BYTES);
    dim3 grid(N_TOTAL / BN, (M_TOTAL + BM - 1) / BM);  // N fastest -> A L2 reuse
    gemm_kernel<<<grid, 128, SMEM_BYTES>>>(out);
}